// round 1
// baseline (speedup 1.0000x reference)
#include <cuda_runtime.h>
#include <cuda_bf16.h>
#include <cstdint>
#include <cmath>

// ---------------------------------------------------------------------------
// Problem constants (fixed shapes)
// ---------------------------------------------------------------------------
#define BB 2
#define TT 2048
#define NE 2048          // N_EMBED
#define NH 16            // N_HEAD
#define NKV 4            // N_KV_HEAD
#define HD 128           // HEAD_DIM
#define MROWS (BB*TT)    // 4096
#define KVDIM (NKV*HD)   // 512

// ---------------------------------------------------------------------------
// Scratch (static device globals; no allocations allowed)
// ---------------------------------------------------------------------------
__device__ float g_q[(size_t)MROWS * NE];       // x@Wq+bq
__device__ float g_k[(size_t)MROWS * KVDIM];    // x@Wk+bk
__device__ float g_v[(size_t)MROWS * KVDIM];    // x@Wv+bv
__device__ float g_o[(size_t)MROWS * NE];       // attention output [B,T,H*D]
__device__ __nv_bfloat16 g_qr[(size_t)BB * NH * TT * HD];   // rope(q) bf16 [B,H,T,D]
__device__ __nv_bfloat16 g_kr[(size_t)BB * NKV * TT * HD];  // rope(k) bf16 [B,KV,T,D]
__device__ float g_cos[TT * (HD/2)];
__device__ float g_sin[TT * (HD/2)];

// ---------------------------------------------------------------------------
// SGEMM: C[M,N] = A[M,K] @ B[K,N] + bias[N]   (all row-major, fp32)
// 128x128 block tile, BK=16, 256 threads, 8x8 per-thread micro-tile.
// M % 128 == 0, N % 128 == 0, K % 16 == 0 (true for all our shapes).
// ---------------------------------------------------------------------------
__device__ __forceinline__ void gemm_body(const float* __restrict__ A,
                                          const float* __restrict__ B,
                                          const float* __restrict__ bias,
                                          float* __restrict__ C,
                                          int M, int N, int K)
{
    __shared__ float As[16 * 128];   // transposed: As[k][m]
    __shared__ float Bs[16 * 128];   // Bs[k][n]

    const int tid = threadIdx.x;     // 0..255
    const int tx  = tid & 15;        // N micro index
    const int ty  = tid >> 4;        // M micro index
    const int m0  = blockIdx.y * 128;
    const int n0  = blockIdx.x * 128;

    float acc[8][8];
    #pragma unroll
    for (int i = 0; i < 8; i++)
        #pragma unroll
        for (int j = 0; j < 8; j++) acc[i][j] = 0.f;

    for (int k0 = 0; k0 < K; k0 += 16) {
        // load A tile (128 rows x 16 cols), store transposed
        #pragma unroll
        for (int s = 0; s < 2; s++) {
            int f   = tid * 2 + s;           // 0..511
            int row = f >> 2;                // 0..127
            int kq  = (f & 3) << 2;          // 0,4,8,12
            float4 av = *(const float4*)&A[(size_t)(m0 + row) * K + k0 + kq];
            As[(kq + 0) * 128 + row] = av.x;
            As[(kq + 1) * 128 + row] = av.y;
            As[(kq + 2) * 128 + row] = av.z;
            As[(kq + 3) * 128 + row] = av.w;
        }
        // load B tile (16 rows x 128 cols)
        #pragma unroll
        for (int s = 0; s < 2; s++) {
            int f   = tid * 2 + s;
            int row = f >> 5;                // 0..15
            int c4  = (f & 31) << 2;         // 0..124
            *(float4*)&Bs[row * 128 + c4] =
                *(const float4*)&B[(size_t)(k0 + row) * N + n0 + c4];
        }
        __syncthreads();

        #pragma unroll
        for (int k = 0; k < 16; k++) {
            float a[8], bv[8];
            *(float4*)&a[0]  = *(float4*)&As[k * 128 + ty * 4];
            *(float4*)&a[4]  = *(float4*)&As[k * 128 + 64 + ty * 4];
            *(float4*)&bv[0] = *(float4*)&Bs[k * 128 + tx * 4];
            *(float4*)&bv[4] = *(float4*)&Bs[k * 128 + 64 + tx * 4];
            #pragma unroll
            for (int i = 0; i < 8; i++)
                #pragma unroll
                for (int j = 0; j < 8; j++)
                    acc[i][j] += a[i] * bv[j];
        }
        __syncthreads();
    }

    // epilogue: add bias, store
    #pragma unroll
    for (int ih = 0; ih < 2; ih++) {
        #pragma unroll
        for (int i = 0; i < 4; i++) {
            int gm = m0 + ih * 64 + ty * 4 + i;
            #pragma unroll
            for (int jh = 0; jh < 2; jh++) {
                int gn = n0 + jh * 64 + tx * 4;
                float4 bv = *(const float4*)&bias[gn];
                float4 o;
                o.x = acc[ih * 4 + i][jh * 4 + 0] + bv.x;
                o.y = acc[ih * 4 + i][jh * 4 + 1] + bv.y;
                o.z = acc[ih * 4 + i][jh * 4 + 2] + bv.z;
                o.w = acc[ih * 4 + i][jh * 4 + 3] + bv.w;
                *(float4*)&C[(size_t)gm * N + gn] = o;
            }
        }
    }
}

__global__ void __launch_bounds__(256)
gemm_bias_kernel(const float* __restrict__ A, const float* __restrict__ B,
                 const float* __restrict__ bias, float* __restrict__ C,
                 int M, int N, int K)
{
    gemm_body(A, B, bias, C, M, N, K);
}

__global__ void __launch_bounds__(256)
gemm_kv_kernel(const float* __restrict__ A,
               const float* __restrict__ B0, const float* __restrict__ bias0, float* __restrict__ C0,
               const float* __restrict__ B1, const float* __restrict__ bias1, float* __restrict__ C1,
               int M, int N, int K)
{
    const float* B    = blockIdx.z ? B1    : B0;
    const float* bias = blockIdx.z ? bias1 : bias0;
    float*       C    = blockIdx.z ? C1    : C0;
    gemm_body(A, B, bias, C, M, N, K);
}

// ---------------------------------------------------------------------------
// RoPE table: angle = fp32(t) * fp32(double-precision freq), matching the
// reference's fp32 pipeline as closely as possible.
// ---------------------------------------------------------------------------
__global__ void __launch_bounds__(256)
rope_table_kernel(float* __restrict__ ct, float* __restrict__ st)
{
    int idx = blockIdx.x * 256 + threadIdx.x;
    if (idx >= TT * (HD/2)) return;
    int t = idx >> 6;
    int i = idx & 63;
    double fr = exp(-((double)(2 * i) / (double)NE) * log(10000.0));
    float ff = (float)fr;
    float ang = __fmul_rn((float)t, ff);
    float s, c;
    sincosf(ang, &s, &c);
    ct[idx] = c;
    st[idx] = s;
}

// rope + bf16 round for Q: [B,T,H,D] fp32 -> [B,H,T,D] bf16
__global__ void __launch_bounds__(256)
rope_q_kernel(const float* __restrict__ q, const float* __restrict__ ct,
              const float* __restrict__ st, __nv_bfloat16* __restrict__ qr)
{
    int idx = blockIdx.x * 256 + threadIdx.x;   // total BB*TT*NH*64
    int i = idx & 63;
    int h = (idx >> 6) & 15;
    int t = (idx >> 10) & 2047;
    int b = idx >> 21;
    size_t src = ((size_t)(b * TT + t)) * NE + h * HD + 2 * i;
    float xr = q[src], xi = q[src + 1];
    float c = ct[t * 64 + i], s = st[t * 64 + i];
    float orr = xr * c - xi * s;
    float oii = xr * s + xi * c;
    size_t dst = ((size_t)((b * NH + h) * TT + t)) * HD + 2 * i;
    qr[dst]     = __float2bfloat16(orr);
    qr[dst + 1] = __float2bfloat16(oii);
}

// rope + bf16 round for K: [B,T,KV,D] fp32 -> [B,KV,T,D] bf16
__global__ void __launch_bounds__(256)
rope_k_kernel(const float* __restrict__ k, const float* __restrict__ ct,
              const float* __restrict__ st, __nv_bfloat16* __restrict__ kr)
{
    int idx = blockIdx.x * 256 + threadIdx.x;   // total BB*TT*NKV*64
    int i = idx & 63;
    int h = (idx >> 6) & 3;
    int t = (idx >> 8) & 2047;
    int b = idx >> 19;
    size_t src = ((size_t)(b * TT + t)) * KVDIM + h * HD + 2 * i;
    float xr = k[src], xi = k[src + 1];
    float c = ct[t * 64 + i], s = st[t * 64 + i];
    float orr = xr * c - xi * s;
    float oii = xr * s + xi * c;
    size_t dst = ((size_t)((b * NKV + h) * TT + t)) * HD + 2 * i;
    kr[dst]     = __float2bfloat16(orr);
    kr[dst + 1] = __float2bfloat16(oii);
}

// ---------------------------------------------------------------------------
// Flash attention (causal, GQA). fp32 SIMT. BM=BN=64, 256 threads.
// attn = softmax(q@k^T) * 2048^-0.5;  o = attn @ v.
// smem: qs[64][128] | kst[128][65] (k transposed) | vs[64][128] | ss[64][68]
// ---------------------------------------------------------------------------
#define ATTN_SMEM_FLOATS (64*128 + 128*65 + 64*128 + 64*68)

__global__ void __launch_bounds__(256)
attn_kernel(const __nv_bfloat16* __restrict__ qr, const __nv_bfloat16* __restrict__ kr,
            const float* __restrict__ v, float* __restrict__ o)
{
    extern __shared__ float sm[];
    float* qs  = sm;                       // 8192
    float* kst = sm + 64 * 128;            // 8320 (stride 65)
    float* vs  = kst + 128 * 65;           // 8192
    float* ss  = vs + 64 * 128;            // 64*68 (stride 68)

    const int tid = threadIdx.x;
    const int mt = blockIdx.x, h = blockIdx.y, b = blockIdx.z;
    const int m0 = mt * 64;
    const int kv = h >> 2;                 // REPEAT = 4

    const __nv_bfloat16* qg = qr + ((size_t)(b * NH + h) * TT + m0) * HD;
    const __nv_bfloat16* kg = kr + ((size_t)(b * NKV + kv) * TT) * HD;
    const float*         vg = v  + ((size_t)b * TT) * KVDIM + kv * HD;

    // load q tile -> qs (fp32)
    for (int idx = tid; idx < 64 * 16; idx += 256) {
        int r  = idx >> 4;
        int d8 = (idx & 15) << 3;
        uint4 u = *(const uint4*)(qg + (size_t)r * HD + d8);
        const __nv_bfloat16* pb = (const __nv_bfloat16*)&u;
        #pragma unroll
        for (int j = 0; j < 8; j++)
            qs[r * 128 + d8 + j] = __bfloat162float(pb[j]);
    }

    float acc[32];
    #pragma unroll
    for (int j = 0; j < 32; j++) acc[j] = 0.f;
    float mrow = -1e30f, lrow = 0.f;

    const int r  = tid >> 2;   // row 0..63 (softmax/AV stage)
    const int cg = tid & 3;    // column group
    const int tx = tid & 15;   // score micro-tile N
    const int ty = tid >> 4;   // score micro-tile M

    const int ntile = mt + 1;  // causal: keys up to m0+63
    for (int jt = 0; jt < ntile; jt++) {
        const int kn = jt * 64;
        __syncthreads();  // previous tile fully consumed (and q loaded, 1st iter)

        // load k tile transposed: kst[d][n]
        for (int idx = tid; idx < 64 * 16; idx += 256) {
            int n  = idx >> 4;
            int d8 = (idx & 15) << 3;
            uint4 u = *(const uint4*)(kg + (size_t)(kn + n) * HD + d8);
            const __nv_bfloat16* pb = (const __nv_bfloat16*)&u;
            #pragma unroll
            for (int j = 0; j < 8; j++)
                kst[(d8 + j) * 65 + n] = __bfloat162float(pb[j]);
        }
        // load v tile: vs[n][c]
        for (int idx = tid; idx < 64 * 32; idx += 256) {
            int n  = idx >> 5;
            int c4 = (idx & 31) << 2;
            *(float4*)&vs[n * 128 + c4] =
                *(const float4*)(vg + (size_t)(kn + n) * KVDIM + c4);
        }
        __syncthreads();

        // scores: s = q @ k^T  (64x64x128), 4x4 micro-tile per thread
        float sacc[4][4];
        #pragma unroll
        for (int i = 0; i < 4; i++)
            #pragma unroll
            for (int j = 0; j < 4; j++) sacc[i][j] = 0.f;

        #pragma unroll 4
        for (int d = 0; d < 128; d++) {
            float a0 = qs[(ty * 4 + 0) * 128 + d];
            float a1 = qs[(ty * 4 + 1) * 128 + d];
            float a2 = qs[(ty * 4 + 2) * 128 + d];
            float a3 = qs[(ty * 4 + 3) * 128 + d];
            float b0 = kst[d * 65 + tx * 4 + 0];
            float b1 = kst[d * 65 + tx * 4 + 1];
            float b2 = kst[d * 65 + tx * 4 + 2];
            float b3 = kst[d * 65 + tx * 4 + 3];
            sacc[0][0] += a0 * b0; sacc[0][1] += a0 * b1; sacc[0][2] += a0 * b2; sacc[0][3] += a0 * b3;
            sacc[1][0] += a1 * b0; sacc[1][1] += a1 * b1; sacc[1][2] += a1 * b2; sacc[1][3] += a1 * b3;
            sacc[2][0] += a2 * b0; sacc[2][1] += a2 * b1; sacc[2][2] += a2 * b2; sacc[2][3] += a2 * b3;
            sacc[3][0] += a3 * b0; sacc[3][1] += a3 * b1; sacc[3][2] += a3 * b2; sacc[3][3] += a3 * b3;
        }
        // causal mask + store scores
        #pragma unroll
        for (int i = 0; i < 4; i++) {
            int gm = m0 + ty * 4 + i;
            #pragma unroll
            for (int j = 0; j < 4; j++) {
                int gn = kn + tx * 4 + j;
                ss[(ty * 4 + i) * 68 + tx * 4 + j] = (gn <= gm) ? sacc[i][j] : -1e30f;
            }
        }
        __syncthreads();

        // row max (each of the 4 threads per row scans the full row)
        float tmax = -1e30f;
        #pragma unroll 8
        for (int n = 0; n < 64; n++) tmax = fmaxf(tmax, ss[r * 68 + n]);
        float mnew  = fmaxf(mrow, tmax);
        float alpha = __expf(mrow - mnew);
        __syncthreads();  // everyone done reading raw scores

        // exp (split across the 4 threads of the row), write p back to ss
        #pragma unroll
        for (int n = cg * 16; n < cg * 16 + 16; n++)
            ss[r * 68 + n] = __expf(ss[r * 68 + n] - mnew);
        mrow = mnew;
        lrow *= alpha;
        #pragma unroll
        for (int j = 0; j < 32; j++) acc[j] *= alpha;
        __syncthreads();

        // AV: acc[c] += p[n] * v[n][c], thread owns cols cg + 4*j
        for (int n = 0; n < 64; n++) {
            float p = ss[r * 68 + n];
            lrow += p;
            #pragma unroll
            for (int j = 0; j < 32; j++)
                acc[j] += p * vs[n * 128 + cg + 4 * j];
        }
    }

    // epilogue: o = acc / l * 2048^-0.5, layout [B,T,H*D]
    const float inv = 0.022097086912079608f / lrow;
    float* og = o + ((size_t)(b * TT + m0 + r)) * NE + h * HD + cg;
    #pragma unroll
    for (int j = 0; j < 32; j++)
        og[4 * j] = acc[j] * inv;
}

// ---------------------------------------------------------------------------
// launch
// ---------------------------------------------------------------------------
extern "C" void kernel_launch(void* const* d_in, const int* in_sizes, int n_in,
                              void* d_out, int out_size)
{
    const float* x  = (const float*)d_in[0];
    const float* Wq = (const float*)d_in[1];
    const float* bq = (const float*)d_in[2];
    const float* Wk = (const float*)d_in[3];
    const float* bk = (const float*)d_in[4];
    const float* Wv = (const float*)d_in[5];
    const float* bv = (const float*)d_in[6];
    const float* Wo = (const float*)d_in[7];
    const float* bo = (const float*)d_in[8];
    float* out = (float*)d_out;

    float *qb, *kb, *vb, *ob, *ct, *st;
    __nv_bfloat16 *qr, *kr;
    cudaGetSymbolAddress((void**)&qb, g_q);
    cudaGetSymbolAddress((void**)&kb, g_k);
    cudaGetSymbolAddress((void**)&vb, g_v);
    cudaGetSymbolAddress((void**)&ob, g_o);
    cudaGetSymbolAddress((void**)&ct, g_cos);
    cudaGetSymbolAddress((void**)&st, g_sin);
    cudaGetSymbolAddress((void**)&qr, g_qr);
    cudaGetSymbolAddress((void**)&kr, g_kr);

    // Q projection: [4096,2048] @ [2048,2048]
    {
        dim3 grid(NE / 128, MROWS / 128, 1);
        gemm_bias_kernel<<<grid, 256>>>(x, Wq, bq, qb, MROWS, NE, NE);
    }
    // K and V projections fused over blockIdx.z: [4096,2048] @ [2048,512]
    {
        dim3 grid(KVDIM / 128, MROWS / 128, 2);
        gemm_kv_kernel<<<grid, 256>>>(x, Wk, bk, kb, Wv, bv, vb, MROWS, KVDIM, NE);
    }
    // RoPE tables + apply
    rope_table_kernel<<<(TT * 64 + 255) / 256, 256>>>(ct, st);
    rope_q_kernel<<<(BB * TT * NH * 64) / 256, 256>>>(qb, ct, st, qr);
    rope_k_kernel<<<(BB * TT * NKV * 64) / 256, 256>>>(kb, ct, st, kr);

    // attention
    {
        size_t smem = (size_t)ATTN_SMEM_FLOATS * sizeof(float);
        cudaFuncSetAttribute(attn_kernel, cudaFuncAttributeMaxDynamicSharedMemorySize, (int)smem);
        dim3 grid(TT / 64, NH, BB);
        attn_kernel<<<grid, 256, smem>>>(qr, kr, vb, ob);
    }

    // output projection: [4096,2048] @ [2048,2048] -> d_out
    {
        dim3 grid(NE / 128, MROWS / 128, 1);
        gemm_bias_kernel<<<grid, 256>>>(ob, Wo, bo, out, MROWS, NE, NE);
    }
}